// round 9
// baseline (speedup 1.0000x reference)
#include <cuda_runtime.h>
#include <cuda_fp16.h>
#include <cstdint>
#include <cstddef>

#define HID 1024
#define BAT 512
#define NL  2
#define TT  32

#define A_BYTES   16384          // 128 rows x 64 halves
#define STG_BYTES 32768          // A + B
#define NSTG 6
#define SMEM_BYTES (NSTG * STG_BYTES)   // 196608, 1 CTA/SM

// ---------------- device scratch ----------------
__device__ __half g_Wc[(size_t)NL * 4 * HID * 2 * HID];  // [l][np][k] gate-interleaved, K-concat
__device__ __half g_thW[(size_t)2 * HID * HID];
__device__ float  g_biasc[NL * 4 * HID];
__device__ __half g_z16[(size_t)BAT * HID];
__device__ __half g_x0[(size_t)BAT * HID];
__device__ __half g_h[NL * 2][(size_t)BAT * HID];        // ping-pong per layer
__device__ float  g_c[NL][(size_t)BAT * HID];

// ---------------- helpers ----------------
__device__ __forceinline__ uint32_t smem_u32(const void* p) {
    return (uint32_t)__cvta_generic_to_shared(p);
}
__device__ __forceinline__ void cp16(uint32_t s, const void* g) {
    asm volatile("cp.async.cg.shared.global [%0], [%1], 16;\n" :: "r"(s), "l"(g));
}
__device__ __forceinline__ void mma16816(float* d, const uint32_t* a, const uint32_t* b) {
    asm volatile(
        "mma.sync.aligned.m16n8k16.row.col.f32.f16.f16.f32 "
        "{%0,%1,%2,%3}, {%4,%5,%6,%7}, {%8,%9}, {%0,%1,%2,%3};\n"
        : "+f"(d[0]), "+f"(d[1]), "+f"(d[2]), "+f"(d[3])
        : "r"(a[0]), "r"(a[1]), "r"(a[2]), "r"(a[3]), "r"(b[0]), "r"(b[1]));
}
#define LDSM4(r, addr)                                                          \
    asm volatile("ldmatrix.sync.aligned.m8n8.x4.shared.b16 {%0,%1,%2,%3}, [%4];"\
        : "=r"((r)[0]), "=r"((r)[1]), "=r"((r)[2]), "=r"((r)[3]) : "r"(addr))

// smem tile rows of 64 halves (128B), classic 8-chunk xor swizzle
__device__ __forceinline__ int swz64(int r, int k) {
    return r * 64 + ((((k >> 3) ^ (r & 7)) << 3) | (k & 7));
}

__device__ __forceinline__ float sigf(float x) {
    return __fdividef(1.f, 1.f + __expf(-x));
}
__device__ __forceinline__ float tanhe(float x) {
    return __fdividef(2.f, 1.f + __expf(-2.f * x)) - 1.f;
}

// ---------------- conversion kernels ----------------
// gate-interleaved: np = 16*(u>>2) + 2*(u&3) + gofs, gofs = {i:0, f:1, g:8, o:9}
__global__ void convert_w_kernel(const float* __restrict__ Wih, const float* __restrict__ Whh) {
    size_t total = (size_t)NL * 4 * HID * 2 * HID;
    for (size_t idx = (size_t)blockIdx.x * blockDim.x + threadIdx.x; idx < total;
         idx += (size_t)gridDim.x * blockDim.x) {
        int k  = (int)(idx & (2 * HID - 1));
        int np = (int)((idx >> 11) & 4095);
        int l  = (int)(idx >> 23);
        int within = np & 15, block = np >> 4;
        int gate = ((within & 8) ? 2 : 0) + (within & 1);
        int tig  = (within & 7) >> 1;
        int u = block * 4 + tig;
        size_t ln = (size_t)l * 4 * HID + (size_t)gate * HID + u;
        float v = (k < HID) ? Wih[ln * HID + k] : Whh[ln * HID + (k - HID)];
        g_Wc[idx] = __float2half(v);
    }
}
__global__ void convert_misc_kernel(const float* __restrict__ z, const float* __restrict__ thW,
                                    const float* __restrict__ emb,
                                    const float* __restrict__ bih, const float* __restrict__ bhh) {
    int total = 2 * HID * HID;
    for (int idx = blockIdx.x * blockDim.x + threadIdx.x; idx < total;
         idx += gridDim.x * blockDim.x) {
        g_thW[idx] = __float2half(thW[idx]);
        if (idx < BAT * HID) {
            g_z16[idx] = __float2half(z[idx]);
            g_x0[idx]  = __float2half(emb[idx & (HID - 1)]);
        }
        if (idx < NL * BAT * HID) ((float*)g_c)[idx] = 0.f;
        if (idx < NL * 4 * HID) {
            int l = idx >> 12, np = idx & 4095;
            int within = np & 15, block = np >> 4;
            int gate = ((within & 8) ? 2 : 0) + (within & 1);
            int tig  = (within & 7) >> 1;
            int u = block * 4 + tig;
            int src = l * 4 * HID + gate * HID + u;
            g_biasc[idx] = bih[src] + bhh[src];
        }
    }
}

// ---------------- fused GEMM (+LSTM cell), k-split warps ----------------
// C[512,N] = [A0|A1][512,K] @ Bw[N,K]^T
// CTA tile 128x128, 8 warps as 2m x 2n x 2k; warp tile 64x64 over alternate k-tiles.
// 6-stage cp.async ring, one barrier per PAIR of 64-half k-tiles.
// End: wk-groups exchange half their accumulators via smem and split the epilogue.
template<int EPI>
__global__ void __launch_bounds__(256, 1)
lstm_gemm(const __half* __restrict__ A0, const __half* __restrict__ A1,
          const __half* __restrict__ Bw, const float* __restrict__ bias,
          float* __restrict__ cptr, __half* __restrict__ hptr,
          float* __restrict__ yptr, int KT)            // KT in 64-half k-tiles (even)
{
    extern __shared__ __half sm[];
    const uint32_t sb = smem_u32(sm);
    const int tid = threadIdx.x, wid = tid >> 5, lane = tid & 31;
    const int g8 = lane >> 2, tig = lane & 3;
    const int wm = wid & 1, wn = (wid >> 1) & 1, wk = wid >> 2;
    const int bm = blockIdx.y * 128, bn = blockIdx.x * 128;
    const int Kh = KT * 64;
    const int NP = KT >> 1;

    float acc[4][8][4];
    #pragma unroll
    for (int a = 0; a < 4; a++)
        #pragma unroll
        for (int b = 0; b < 8; b++)
            #pragma unroll
            for (int d = 0; d < 4; d++) acc[a][b][d] = 0.f;

    // slice-0 tile-relative byte offsets; slice s: off ^ (s<<5)
    uint32_t aoff[4], boff[4];
    {
        int arow = lane & 15, ac = (lane >> 4) << 3;
        int brow = (lane & 7) + ((lane & 16) >> 1), bc = lane & 8;
        #pragma unroll
        for (int mt = 0; mt < 4; mt++)
            aoff[mt] = 2 * swz64(wm * 64 + mt * 16 + arow, ac);
        #pragma unroll
        for (int nt = 0; nt < 4; nt++)
            boff[nt] = A_BYTES + 2 * swz64(wn * 64 + nt * 16 + brow, bc);
    }

    auto fill = [&](int kt) {
        int st = kt % NSTG;
        int k0 = kt << 6;
        const __half* Ap; int ks;
        if (k0 < HID) { Ap = A0; ks = k0; } else { Ap = A1; ks = k0 - HID; }
        uint32_t ab = sb + st * STG_BYTES, bb = ab + A_BYTES;
        int r0 = tid >> 3, c = tid & 7;
        #pragma unroll
        for (int i = 0; i < 4; i++) {                  // 128 rows x 8 chunks, 256 thr
            int r = r0 + i * 32;
            uint32_t off = 2 * swz64(r, c << 3);
            cp16(ab + off, Ap + (size_t)(bm + r) * HID + ks + (c << 3));
            cp16(bb + off, Bw + (size_t)(bn + r) * Kh + k0 + (c << 3));
        }
    };

    fill(0); fill(1); asm volatile("cp.async.commit_group;\n");
    if (NP > 1) { fill(2); fill(3); asm volatile("cp.async.commit_group;\n"); }

    for (int i = 0; i < NP; i++) {
        if (i + 1 < NP) asm volatile("cp.async.wait_group 1;\n");
        else            asm volatile("cp.async.wait_group 0;\n");
        __syncthreads();
        if (i + 2 < NP) {
            fill(2 * i + 4); fill(2 * i + 5);
            asm volatile("cp.async.commit_group;\n");
        }

        // group wk consumes k-tile 2i+wk
        const uint32_t tb = sb + ((2 * i + wk) % NSTG) * STG_BYTES;

        uint32_t af[2][4][4], bf[2][4][4];
        #pragma unroll
        for (int mt = 0; mt < 4; mt++) LDSM4(af[0][mt], tb + aoff[mt]);
        #pragma unroll
        for (int nt = 0; nt < 4; nt++) LDSM4(bf[0][nt], tb + boff[nt]);

        #pragma unroll
        for (int s = 0; s < 4; s++) {
            const int cb = s & 1, nb = cb ^ 1;
            if (s < 3) {
                const uint32_t x = (uint32_t)(s + 1) << 5;
                #pragma unroll
                for (int mt = 0; mt < 4; mt++) LDSM4(af[nb][mt], tb + (aoff[mt] ^ x));
                #pragma unroll
                for (int nt = 0; nt < 4; nt++) LDSM4(bf[nb][nt], tb + (boff[nt] ^ x));
            }
            #pragma unroll
            for (int mt = 0; mt < 4; mt++) {
                #pragma unroll
                for (int nt = 0; nt < 4; nt++) {
                    mma16816(acc[mt][2 * nt],     af[cb][mt], &bf[cb][nt][0]);
                    mma16816(acc[mt][2 * nt + 1], af[cb][mt], &bf[cb][nt][2]);
                }
            }
        }
    }

    // ---------------- accumulator exchange (k-split reduction) ----------------
    // wk0 stores mt2,3; wk1 stores mt0,1. Each then adds the peer's half and
    // runs the epilogue on its own half (wk0: mt0,1 = rows 0-31; wk1: mt2,3).
    __syncthreads();
    {
        float* xb = (float*)sm;
        const int pairIdx = wm * 2 + wn;               // 0..3
        float* myStore = xb + (size_t)(pairIdx * 2 + wk) * 2048;
        const int stMt = wk ? 0 : 2;
        #pragma unroll
        for (int mtr = 0; mtr < 2; mtr++)
            #pragma unroll
            for (int nn = 0; nn < 8; nn++)
                #pragma unroll
                for (int d = 0; d < 4; d++)
                    myStore[(mtr * 32 + nn * 4 + d) * 32 + lane] = acc[stMt + mtr][nn][d];
        __syncthreads();
        float* peer = xb + (size_t)(pairIdx * 2 + (wk ^ 1)) * 2048;
        const int myMt = wk ? 2 : 0;
        #pragma unroll
        for (int mtr = 0; mtr < 2; mtr++)
            #pragma unroll
            for (int nn = 0; nn < 8; nn++)
                #pragma unroll
                for (int d = 0; d < 4; d++)
                    acc[myMt + mtr][nn][d] += peer[(mtr * 32 + nn * 4 + d) * 32 + lane];

        // ---------------- epilogue on my half ----------------
        if (EPI == 0) {
            #pragma unroll
            for (int p = 0; p < 4; p++) {
                int nb = bn + wn * 64 + p * 16 + 2 * tig;
                float bi = bias[nb], bff = bias[nb + 1], bg = bias[nb + 8], bo = bias[nb + 9];
                int u = (bn >> 2) + wn * 16 + p * 4 + tig;
                #pragma unroll
                for (int mtr = 0; mtr < 2; mtr++) {
                    int mt = myMt + mtr;
                    #pragma unroll
                    for (int hr = 0; hr < 2; hr++) {
                        int b = bm + wm * 64 + mt * 16 + g8 + hr * 8;
                        int d = hr * 2;
                        float ig = acc[mt][2 * p][d]         + bi;
                        float fg = acc[mt][2 * p][d + 1]     + bff;
                        float gg = acc[mt][2 * p + 1][d]     + bg;
                        float og = acc[mt][2 * p + 1][d + 1] + bo;
                        size_t ci = (size_t)b * HID + u;
                        float cn = sigf(fg) * cptr[ci] + sigf(ig) * tanhe(gg);
                        float hn = sigf(og) * tanhe(cn);
                        cptr[ci] = cn;
                        hptr[ci] = __float2half(hn);
                        if (yptr) yptr[ci] = hn;
                    }
                }
            }
        } else {
            #pragma unroll
            for (int mtr = 0; mtr < 2; mtr++) {
                int mt = myMt + mtr;
                int r0 = bm + wm * 64 + mt * 16 + g8;
                #pragma unroll
                for (int nn = 0; nn < 8; nn++) {
                    int col = bn + wn * 64 + nn * 8 + 2 * tig;
                    float b0 = bias[col], b1 = bias[col + 1];
                    int l2 = col >> 10, j = col & (HID - 1);
                    __half2 v0 = __floats2half2_rn(tanhe(acc[mt][nn][0] + b0),
                                                   tanhe(acc[mt][nn][1] + b1));
                    __half2 v1 = __floats2half2_rn(tanhe(acc[mt][nn][2] + b0),
                                                   tanhe(acc[mt][nn][3] + b1));
                    size_t lofs = (size_t)l2 * 2 * BAT * HID;   // ping buffer 0
                    *(__half2*)(hptr + lofs + (size_t)r0 * HID + j)       = v0;
                    *(__half2*)(hptr + lofs + (size_t)(r0 + 8) * HID + j) = v1;
                }
            }
        }
    }
}

// ---------------- launch ----------------
extern "C" void kernel_launch(void* const* d_in, const int* in_sizes, int n_in,
                              void* d_out, int out_size)
{
    const float* z   = (const float*)d_in[0];
    const float* thW = (const float*)d_in[1];
    const float* thb = (const float*)d_in[2];
    const float* emb = (const float*)d_in[3];
    const float* Wih = (const float*)d_in[4];
    const float* Whh = (const float*)d_in[5];
    const float* bih = (const float*)d_in[6];
    const float* bhh = (const float*)d_in[7];
    float* out = (float*)d_out;

    __half *Wc, *thWc, *z16, *x0, *h;
    float *c, *biasc;
    cudaGetSymbolAddress((void**)&Wc,    g_Wc);
    cudaGetSymbolAddress((void**)&thWc,  g_thW);
    cudaGetSymbolAddress((void**)&z16,   g_z16);
    cudaGetSymbolAddress((void**)&x0,    g_x0);
    cudaGetSymbolAddress((void**)&h,     g_h);
    cudaGetSymbolAddress((void**)&c,     g_c);
    cudaGetSymbolAddress((void**)&biasc, g_biasc);

    cudaFuncSetAttribute(lstm_gemm<0>, cudaFuncAttributeMaxDynamicSharedMemorySize, SMEM_BYTES);
    cudaFuncSetAttribute(lstm_gemm<1>, cudaFuncAttributeMaxDynamicSharedMemorySize, SMEM_BYTES);

    auto hb = [&](int l, int p) { return h + ((size_t)l * 2 + p) * BAT * HID; };

    convert_w_kernel<<<1024, 256>>>(Wih, Whh);
    convert_misc_kernel<<<1024, 256>>>(z, thW, emb, bih, bhh);

    // h0 = tanh(z @ to_h_W^T + to_h_b): M=512, N=2048, K=1024 -> ping buffer 0
    lstm_gemm<1><<<dim3(16, 4), 256, SMEM_BYTES>>>(z16, z16, thWc, thb,
                                                   nullptr, h, nullptr, 16);

    for (int t = 0; t < TT; t++) {
        int p = t & 1;
        for (int l = 0; l < NL; l++) {
            const __half* Ain  = (l == 0) ? (t == 0 ? x0 : hb(1, p)) : hb(0, p ^ 1);
            const __half* Arec = hb(l, p);
            lstm_gemm<0><<<dim3(32, 4), 256, SMEM_BYTES>>>(
                Ain, Arec,
                Wc + (size_t)l * 4 * HID * 2 * HID,
                biasc + l * 4 * HID,
                c + (size_t)l * BAT * HID,
                hb(l, p ^ 1),
                (l == NL - 1) ? out + (size_t)t * BAT * HID : nullptr,
                32);
        }
    }
}

// round 10
// speedup vs baseline: 5.1183x; 5.1183x over previous
#include <cuda_runtime.h>
#include <cuda_fp16.h>
#include <cstdint>
#include <cstddef>

#define HID 1024
#define BAT 512
#define NL  2
#define TT  32

#define A_BYTES   16384          // 128 rows x 64 halves
#define STG_BYTES 32768          // A + B
#define NSTG 6
#define SMEM_BYTES (NSTG * STG_BYTES)   // 196608, 1 CTA/SM

// ---------------- device scratch ----------------
__device__ __half g_Wc[(size_t)NL * 4 * HID * 2 * HID];  // [l][np][k] gate-interleaved, K-concat
__device__ __half g_thW[(size_t)2 * HID * HID];
__device__ float  g_biasc[NL * 4 * HID];
__device__ __half g_z16[(size_t)BAT * HID];
__device__ __half g_x0[(size_t)BAT * HID];
__device__ __half g_h[NL * 2][(size_t)BAT * HID];        // ping-pong per layer
__device__ float  g_c[NL][(size_t)BAT * HID];

// ---------------- helpers ----------------
__device__ __forceinline__ uint32_t smem_u32(const void* p) {
    return (uint32_t)__cvta_generic_to_shared(p);
}
__device__ __forceinline__ void cp16(uint32_t s, const void* g) {
    asm volatile("cp.async.cg.shared.global [%0], [%1], 16;\n" :: "r"(s), "l"(g));
}
__device__ __forceinline__ void mma16816(float* d, const uint32_t* a, const uint32_t* b) {
    asm volatile(
        "mma.sync.aligned.m16n8k16.row.col.f32.f16.f16.f32 "
        "{%0,%1,%2,%3}, {%4,%5,%6,%7}, {%8,%9}, {%0,%1,%2,%3};\n"
        : "+f"(d[0]), "+f"(d[1]), "+f"(d[2]), "+f"(d[3])
        : "r"(a[0]), "r"(a[1]), "r"(a[2]), "r"(a[3]), "r"(b[0]), "r"(b[1]));
}
#define LDSM4(r, addr)                                                          \
    asm volatile("ldmatrix.sync.aligned.m8n8.x4.shared.b16 {%0,%1,%2,%3}, [%4];"\
        : "=r"((r)[0]), "=r"((r)[1]), "=r"((r)[2]), "=r"((r)[3]) : "r"(addr))

// smem tile rows of 64 halves (128B), classic 8-chunk xor swizzle
__device__ __forceinline__ int swz64(int r, int k) {
    return r * 64 + ((((k >> 3) ^ (r & 7)) << 3) | (k & 7));
}

__device__ __forceinline__ float sigf(float x) {
    return __fdividef(1.f, 1.f + __expf(-x));
}
__device__ __forceinline__ float tanhe(float x) {
    return __fdividef(2.f, 1.f + __expf(-2.f * x)) - 1.f;
}

// ---------------- conversion kernels ----------------
// gate-interleaved: np = 16*(u>>2) + 2*(u&3) + gofs, gofs = {i:0, f:1, g:8, o:9}
__global__ void convert_w_kernel(const float* __restrict__ Wih, const float* __restrict__ Whh) {
    size_t total = (size_t)NL * 4 * HID * 2 * HID;
    for (size_t idx = (size_t)blockIdx.x * blockDim.x + threadIdx.x; idx < total;
         idx += (size_t)gridDim.x * blockDim.x) {
        int k  = (int)(idx & (2 * HID - 1));
        int np = (int)((idx >> 11) & 4095);
        int l  = (int)(idx >> 23);
        int within = np & 15, block = np >> 4;
        int gate = ((within & 8) ? 2 : 0) + (within & 1);
        int tig  = (within & 7) >> 1;
        int u = block * 4 + tig;
        size_t ln = (size_t)l * 4 * HID + (size_t)gate * HID + u;
        float v = (k < HID) ? Wih[ln * HID + k] : Whh[ln * HID + (k - HID)];
        g_Wc[idx] = __float2half(v);
    }
}
__global__ void convert_misc_kernel(const float* __restrict__ z, const float* __restrict__ thW,
                                    const float* __restrict__ emb,
                                    const float* __restrict__ bih, const float* __restrict__ bhh) {
    int total = 2 * HID * HID;
    for (int idx = blockIdx.x * blockDim.x + threadIdx.x; idx < total;
         idx += gridDim.x * blockDim.x) {
        g_thW[idx] = __float2half(thW[idx]);
        if (idx < BAT * HID) {
            g_z16[idx] = __float2half(z[idx]);
            g_x0[idx]  = __float2half(emb[idx & (HID - 1)]);
        }
        if (idx < NL * BAT * HID) ((float*)g_c)[idx] = 0.f;
        if (idx < NL * 4 * HID) {
            int l = idx >> 12, np = idx & 4095;
            int within = np & 15, block = np >> 4;
            int gate = ((within & 8) ? 2 : 0) + (within & 1);
            int tig  = (within & 7) >> 1;
            int u = block * 4 + tig;
            int src = l * 4 * HID + gate * HID + u;
            g_biasc[idx] = bih[src] + bhh[src];
        }
    }
}

// ---------------- fused GEMM (+LSTM cell), static k-split ----------------
// C[512,N] = [A0|A1][512,K] @ Bw[N,K]^T
// CTA tile 128x128, 16 warps as 4m x 2n x 2k; warp tile 32x64 over alternate
// k-tiles. 6-stage cp.async ring, one barrier per PAIR of k-tiles.
// End: warp wid exchanges its non-owned mt-half with warp wid^8 via smem;
// ALL accumulator indexing is compile-time (mt loops + runtime guard).
template<int EPI>
__global__ void __launch_bounds__(512)
lstm_gemm(const __half* __restrict__ A0, const __half* __restrict__ A1,
          const __half* __restrict__ Bw, const float* __restrict__ bias,
          float* __restrict__ cptr, __half* __restrict__ hptr,
          float* __restrict__ yptr, int KT)            // KT in 64-half k-tiles (even)
{
    extern __shared__ __half sm[];
    const uint32_t sb = smem_u32(sm);
    const int tid = threadIdx.x, wid = tid >> 5, lane = tid & 31;
    const int g8 = lane >> 2, tig = lane & 3;
    const int wm = wid & 3, wn = (wid >> 2) & 1, wk = wid >> 3;
    const int bm = blockIdx.y * 128, bn = blockIdx.x * 128;
    const int Kh = KT * 64;
    const int NP = KT >> 1;

    float acc[2][8][4];
    #pragma unroll
    for (int a = 0; a < 2; a++)
        #pragma unroll
        for (int b = 0; b < 8; b++)
            #pragma unroll
            for (int d = 0; d < 4; d++) acc[a][b][d] = 0.f;

    // slice-0 tile-relative byte offsets; slice s: off ^ (s<<5)
    uint32_t aoff[2], boff[4];
    {
        int arow = lane & 15, ac = (lane >> 4) << 3;
        int brow = (lane & 7) + ((lane & 16) >> 1), bc = lane & 8;
        #pragma unroll
        for (int mt = 0; mt < 2; mt++)
            aoff[mt] = 2 * swz64(wm * 32 + mt * 16 + arow, ac);
        #pragma unroll
        for (int nt = 0; nt < 4; nt++)
            boff[nt] = A_BYTES + 2 * swz64(wn * 64 + nt * 16 + brow, bc);
    }

    auto fill = [&](int kt) {
        int st = kt % NSTG;
        int k0 = kt << 6;
        const __half* Ap; int ks;
        if (k0 < HID) { Ap = A0; ks = k0; } else { Ap = A1; ks = k0 - HID; }
        uint32_t ab = sb + st * STG_BYTES, bb = ab + A_BYTES;
        #pragma unroll
        for (int i = 0; i < 2; i++) {                  // 1024 chunks of 16B each tile
            int idx = tid + i * 512;
            int r = idx >> 3, c = idx & 7;
            uint32_t off = 2 * swz64(r, c << 3);
            cp16(ab + off, Ap + (size_t)(bm + r) * HID + ks + (c << 3));
            cp16(bb + off, Bw + (size_t)(bn + r) * Kh + k0 + (c << 3));
        }
    };

    fill(0); fill(1); asm volatile("cp.async.commit_group;\n");
    if (NP > 1) { fill(2); fill(3); asm volatile("cp.async.commit_group;\n"); }

    for (int i = 0; i < NP; i++) {
        if (i + 1 < NP) asm volatile("cp.async.wait_group 1;\n");
        else            asm volatile("cp.async.wait_group 0;\n");
        __syncthreads();
        if (i + 2 < NP) {
            fill(2 * i + 4); fill(2 * i + 5);
            asm volatile("cp.async.commit_group;\n");
        }

        // group wk consumes k-tile 2i+wk
        const uint32_t tb = sb + ((2 * i + wk) % NSTG) * STG_BYTES;

        #pragma unroll
        for (int s = 0; s < 4; s++) {
            const uint32_t x = (uint32_t)s << 5;
            uint32_t af[2][4], bf[4][4];
            #pragma unroll
            for (int mt = 0; mt < 2; mt++) LDSM4(af[mt], tb + (aoff[mt] ^ x));
            #pragma unroll
            for (int nt = 0; nt < 4; nt++) LDSM4(bf[nt], tb + (boff[nt] ^ x));
            #pragma unroll
            for (int mt = 0; mt < 2; mt++) {
                #pragma unroll
                for (int nt = 0; nt < 4; nt++) {
                    mma16816(acc[mt][2 * nt],     af[mt], &bf[nt][0]);
                    mma16816(acc[mt][2 * nt + 1], af[mt], &bf[nt][2]);
                }
            }
        }
    }

    // ---------------- k-split reduction (static indices only) ----------------
    __syncthreads();
    {
        float* xb = (float*)sm;
        float* slot = xb + (size_t)wid * 1024;         // 32 floats x 32 lanes
        #pragma unroll
        for (int mt = 0; mt < 2; mt++) if (mt != wk) {
            #pragma unroll
            for (int nn = 0; nn < 8; nn++)
                #pragma unroll
                for (int d = 0; d < 4; d++)
                    slot[(nn * 4 + d) * 32 + lane] = acc[mt][nn][d];
        }
        __syncthreads();
        const float* peer = xb + (size_t)(wid ^ 8) * 1024;
        #pragma unroll
        for (int mt = 0; mt < 2; mt++) if (mt == wk) {
            #pragma unroll
            for (int nn = 0; nn < 8; nn++)
                #pragma unroll
                for (int d = 0; d < 4; d++)
                    acc[mt][nn][d] += peer[(nn * 4 + d) * 32 + lane];
        }
    }

    // ---------------- epilogue: warp handles its own mt == wk half ----------
    if (EPI == 0) {
        #pragma unroll
        for (int mt = 0; mt < 2; mt++) if (mt == wk) {
            #pragma unroll
            for (int nt = 0; nt < 4; nt++) {
                int nb = bn + wn * 64 + nt * 16 + 2 * tig;
                float bi = bias[nb], bff = bias[nb + 1], bg = bias[nb + 8], bo = bias[nb + 9];
                int u = (bn >> 2) + wn * 16 + nt * 4 + tig;
                #pragma unroll
                for (int hr = 0; hr < 2; hr++) {
                    int b = bm + wm * 32 + mt * 16 + g8 + hr * 8;
                    int d = hr * 2;
                    float ig = acc[mt][2 * nt][d]         + bi;
                    float fg = acc[mt][2 * nt][d + 1]     + bff;
                    float gg = acc[mt][2 * nt + 1][d]     + bg;
                    float og = acc[mt][2 * nt + 1][d + 1] + bo;
                    size_t ci = (size_t)b * HID + u;
                    float cn = sigf(fg) * cptr[ci] + sigf(ig) * tanhe(gg);
                    float hn = sigf(og) * tanhe(cn);
                    cptr[ci] = cn;
                    hptr[ci] = __float2half(hn);
                    if (yptr) yptr[ci] = hn;
                }
            }
        }
    } else {
        #pragma unroll
        for (int mt = 0; mt < 2; mt++) if (mt == wk) {
            int r0 = bm + wm * 32 + mt * 16 + g8;
            #pragma unroll
            for (int nn = 0; nn < 8; nn++) {
                int col = bn + wn * 64 + nn * 8 + 2 * tig;
                float b0 = bias[col], b1 = bias[col + 1];
                int l2 = col >> 10, j = col & (HID - 1);
                __half2 v0 = __floats2half2_rn(tanhe(acc[mt][nn][0] + b0),
                                               tanhe(acc[mt][nn][1] + b1));
                __half2 v1 = __floats2half2_rn(tanhe(acc[mt][nn][2] + b0),
                                               tanhe(acc[mt][nn][3] + b1));
                size_t lofs = (size_t)l2 * 2 * BAT * HID;   // ping buffer 0
                *(__half2*)(hptr + lofs + (size_t)r0 * HID + j)       = v0;
                *(__half2*)(hptr + lofs + (size_t)(r0 + 8) * HID + j) = v1;
            }
        }
    }
}

// ---------------- launch ----------------
extern "C" void kernel_launch(void* const* d_in, const int* in_sizes, int n_in,
                              void* d_out, int out_size)
{
    const float* z   = (const float*)d_in[0];
    const float* thW = (const float*)d_in[1];
    const float* thb = (const float*)d_in[2];
    const float* emb = (const float*)d_in[3];
    const float* Wih = (const float*)d_in[4];
    const float* Whh = (const float*)d_in[5];
    const float* bih = (const float*)d_in[6];
    const float* bhh = (const float*)d_in[7];
    float* out = (float*)d_out;

    __half *Wc, *thWc, *z16, *x0, *h;
    float *c, *biasc;
    cudaGetSymbolAddress((void**)&Wc,    g_Wc);
    cudaGetSymbolAddress((void**)&thWc,  g_thW);
    cudaGetSymbolAddress((void**)&z16,   g_z16);
    cudaGetSymbolAddress((void**)&x0,    g_x0);
    cudaGetSymbolAddress((void**)&h,     g_h);
    cudaGetSymbolAddress((void**)&c,     g_c);
    cudaGetSymbolAddress((void**)&biasc, g_biasc);

    cudaFuncSetAttribute(lstm_gemm<0>, cudaFuncAttributeMaxDynamicSharedMemorySize, SMEM_BYTES);
    cudaFuncSetAttribute(lstm_gemm<1>, cudaFuncAttributeMaxDynamicSharedMemorySize, SMEM_BYTES);

    auto hb = [&](int l, int p) { return h + ((size_t)l * 2 + p) * BAT * HID; };

    convert_w_kernel<<<1024, 256>>>(Wih, Whh);
    convert_misc_kernel<<<1024, 256>>>(z, thW, emb, bih, bhh);

    // h0 = tanh(z @ to_h_W^T + to_h_b): M=512, N=2048, K=1024 -> ping buffer 0
    lstm_gemm<1><<<dim3(16, 4), 512, SMEM_BYTES>>>(z16, z16, thWc, thb,
                                                   nullptr, h, nullptr, 16);

    for (int t = 0; t < TT; t++) {
        int p = t & 1;
        for (int l = 0; l < NL; l++) {
            const __half* Ain  = (l == 0) ? (t == 0 ? x0 : hb(1, p)) : hb(0, p ^ 1);
            const __half* Arec = hb(l, p);
            lstm_gemm<0><<<dim3(32, 4), 512, SMEM_BYTES>>>(
                Ain, Arec,
                Wc + (size_t)l * 4 * HID * 2 * HID,
                biasc + l * 4 * HID,
                c + (size_t)l * BAT * HID,
                hb(l, p ^ 1),
                (l == NL - 1) ? out + (size_t)t * BAT * HID : nullptr,
                32);
        }
    }
}